// round 8
// baseline (speedup 1.0000x reference)
#include <cuda_runtime.h>

constexpr int Bc = 512;
constexpr int Lc = 200;
constexpr int Ec = 64;

// ---------------- smem layout (floats) ----------------
constexpr int WSP    = 54;                        // ws[64][54]: ws[j][c], c in [0,48): K|V|Q cols
constexpr int WS_OFF = 0;
constexpr int XTP    = 132;                       // xT[64][132]: xT[j][t_local]
constexpr int XT_OFF = WS_OFF + 64 * WSP;         // 3456 (16B aligned)
constexpr int KTS    = 208;                       // kt[16][208]: kt[d][t]
constexpr int KT_OFF = XT_OFF + 64 * XTP;         // 11904
constexpr int QS_OFF = KT_OFF + 16 * KTS;         // q[200][16] (pre-scaled by 0.25*log2e)
constexpr int VS_OFF = QS_OFF + Lc * 16;          // v[200][16]
constexpr int WC_OFF = VS_OFF + Lc * 16;          // col sums [200]
constexpr int SP_OFF = WC_OFF + Lc + 8;           // partials [16][16]
constexpr int SM1_F  = SP_OFF + 256;              // 22096 floats = 88384 B

__device__ __forceinline__ float ex2f(float x) {
    float y;
    asm("ex2.approx.ftz.f32 %0, %1;" : "=f"(y) : "f"(x));
    return y;
}

extern __shared__ float sw[];

__global__ void __launch_bounds__(256, 2)
attn_head_kernel(const float* __restrict__ input,
                 const int* __restrict__ mask,
                 const float* __restrict__ pos_enc,
                 const float* __restrict__ Wk, const float* __restrict__ bk,
                 const float* __restrict__ Wv, const float* __restrict__ bv,
                 const float* __restrict__ Wq, const float* __restrict__ bq,
                 const float* __restrict__ Wf, const float* __restrict__ bf,
                 float* __restrict__ out) {
    const int tid  = threadIdx.x;
    const int lane = tid & 31;
    const int wid  = tid >> 5;
    const int b    = blockIdx.x >> 2;
    const int h    = blockIdx.x & 3;

    // ---- len (prefix mask; mask is int32) ----
    int pred = (tid < Lc) && (mask[(size_t)b * Lc + tid] != 0);
    const int len = __syncthreads_count(pred);

    // ---- phase 0: weights j-major: ws[j][c], c = m*16+i ----
    // lanes span j -> coalesced LDG from Wm[(h*16+i)*64 + j]
    for (int idx = tid; idx < 64 * 48; idx += 256) {
        int c = idx >> 6, j = idx & 63;
        int m = c >> 4, i = c & 15;
        const float* Wm = (m == 0) ? Wk : ((m == 1) ? Wv : Wq);
        sw[WS_OFF + j * WSP + c] = Wm[(h * 16 + i) * 64 + j];
    }
    if (tid < Lc) sw[WC_OFF + tid] = 0.0f;
    __syncthreads();

    // ---- phase 1: register-tiled GEMM [len,64]x[64,48] ----
    // threadgrid: 32 rowgrps (4 rows) x 8 colgrps (6 cols); tile = 128 rows
    const int rowgrp = tid >> 3;          // 0..31
    const int colgrp = tid & 7;           // 0..7
    const int R0 = rowgrp * 4;            // local row base
    const int c0 = colgrp * 6;            // output col base (0..42)
    const float QSC = 0.36067376022224085f;   // 0.25 * log2(e)

    // per-thread bias for its 6 cols
    float bias[6];
#pragma unroll
    for (int cc = 0; cc < 6; cc++) {
        int c = c0 + cc, m = c >> 4, i = c & 15;
        bias[cc] = (m == 0) ? bk[h * 16 + i] : ((m == 1) ? bv[h * 16 + i] : bq[h * 16 + i]);
    }

    const int ntiles = (len + 127) >> 7;
    for (int tile = 0; tile < ntiles; tile++) {
        const int tb = tile * 128;
        // stage xT[j][t] = input[tb+t][j] + pos_enc[tb+t][j]
        const float4* in4 = (const float4*)(input + ((size_t)b * Lc + tb) * Ec);
        const float4* pe4 = (const float4*)(pos_enc + (size_t)tb * Ec);
#pragma unroll
        for (int v = 0; v < 8; v++) {
            int f = tid + v * 256;            // 0..2047
            int t = f >> 4, e0 = (f & 15) * 4;
            float4 val = make_float4(0.f, 0.f, 0.f, 0.f);
            if (tb + t < Lc) {
                float4 a = in4[f], p = pe4[f];
                val = make_float4(a.x + p.x, a.y + p.y, a.z + p.z, a.w + p.w);
            }
            sw[XT_OFF + (e0 + 0) * XTP + t] = val.x;
            sw[XT_OFF + (e0 + 1) * XTP + t] = val.y;
            sw[XT_OFF + (e0 + 2) * XTP + t] = val.z;
            sw[XT_OFF + (e0 + 3) * XTP + t] = val.w;
        }
        __syncthreads();

        if (tb + R0 < len) {
            float acc[4][6];
#pragma unroll
            for (int rr = 0; rr < 4; rr++)
#pragma unroll
                for (int cc = 0; cc < 6; cc++) acc[rr][cc] = 0.f;

#pragma unroll 8
            for (int j = 0; j < 64; j++) {
                float4 xv = *(const float4*)(sw + XT_OFF + j * XTP + R0);
                const float* wr = sw + WS_OFF + j * WSP + c0;
                float2 w01 = *(const float2*)(wr + 0);
                float2 w23 = *(const float2*)(wr + 2);
                float2 w45 = *(const float2*)(wr + 4);
                float wv[6] = {w01.x, w01.y, w23.x, w23.y, w45.x, w45.y};
                float xr[4] = {xv.x, xv.y, xv.z, xv.w};
#pragma unroll
                for (int rr = 0; rr < 4; rr++)
#pragma unroll
                    for (int cc = 0; cc < 6; cc++)
                        acc[rr][cc] = fmaf(xr[rr], wv[cc], acc[rr][cc]);
            }

            // epilogue: scatter into kt / vs / qs
#pragma unroll
            for (int rr = 0; rr < 4; rr++) {
                int t = tb + R0 + rr;
                if (t < len) {
#pragma unroll
                    for (int cc = 0; cc < 6; cc++) {
                        int c = c0 + cc;
                        float v = acc[rr][cc] + bias[cc];
                        if (c < 16)       sw[KT_OFF + c * KTS + t] = v;
                        else if (c < 32)  sw[VS_OFF + t * 16 + (c - 16)] = v;
                        else              sw[QS_OFF + t * 16 + (c - 32)] = v * QSC;
                    }
                }
            }
        }
        __syncthreads();
    }

    // ---- phase 2: scores (log2 domain) + softmax + column sums ----
    // 8 query rows per warp iteration; lane owns keys kb*64 + lane*2 + {0,1}
    // D split into 4 quarters of 4 dims.
    const int nb = (len + 63) >> 6;              // 1..4 k-blocks of 64
    float wacc[4][2];
#pragma unroll
    for (int kb = 0; kb < 4; kb++) { wacc[kb][0] = 0.f; wacc[kb][1] = 0.f; }

    for (int qb = wid * 8; qb < len; qb += 64) {
        float a[4][8][2];                         // [kb][q][key]
#pragma unroll
        for (int kb = 0; kb < 4; kb++)
#pragma unroll
            for (int qq = 0; qq < 8; qq++) { a[kb][qq][0] = 0.f; a[kb][qq][1] = 0.f; }

#pragma unroll
        for (int qt = 0; qt < 4; qt++) {
            float qv[8][4];
#pragma unroll
            for (int qq = 0; qq < 8; qq++) {
                int q = qb + qq; q = (q < len) ? q : 0;
                float4 v = *(const float4*)(sw + QS_OFF + q * 16 + qt * 4);
                qv[qq][0] = v.x; qv[qq][1] = v.y; qv[qq][2] = v.z; qv[qq][3] = v.w;
            }
#pragma unroll
            for (int kb = 0; kb < 4; kb++) {
                if (kb < nb) {
                    const float* kp = sw + KT_OFF + (qt * 4) * KTS + kb * 64 + lane * 2;
#pragma unroll
                    for (int j = 0; j < 4; j++) {
                        float2 kt2 = *(const float2*)(kp + j * KTS);
#pragma unroll
                        for (int qq = 0; qq < 8; qq++) {
                            a[kb][qq][0] = fmaf(kt2.x, qv[qq][j], a[kb][qq][0]);
                            a[kb][qq][1] = fmaf(kt2.y, qv[qq][j], a[kb][qq][1]);
                        }
                    }
                }
            }
        }

        // exp (in place) + row sums
        float z[8];
#pragma unroll
        for (int qq = 0; qq < 8; qq++) z[qq] = 0.f;
#pragma unroll
        for (int kb = 0; kb < 4; kb++) {
            if (kb < nb) {
                const int k0 = kb * 64 + lane * 2;
                const bool ok0 = (k0 + 0) < len;
                const bool ok1 = (k0 + 1) < len;
#pragma unroll
                for (int qq = 0; qq < 8; qq++) {
                    float e0 = ok0 ? ex2f(a[kb][qq][0]) : 0.f;
                    float e1 = ok1 ? ex2f(a[kb][qq][1]) : 0.f;
                    a[kb][qq][0] = e0; a[kb][qq][1] = e1;
                    z[qq] += e0 + e1;
                }
            }
        }

#pragma unroll
        for (int o = 16; o; o >>= 1) {
#pragma unroll
            for (int qq = 0; qq < 8; qq++)
                z[qq] += __shfl_xor_sync(0xffffffffu, z[qq], o);
        }
        float inv[8];
#pragma unroll
        for (int qq = 0; qq < 8; qq++)
            inv[qq] = (qb + qq < len) ? __fdividef(1.0f, z[qq]) : 0.0f;
#pragma unroll
        for (int kb = 0; kb < 4; kb++) {
            if (kb < nb) {
#pragma unroll
                for (int qq = 0; qq < 8; qq++) {
                    wacc[kb][0] = fmaf(a[kb][qq][0], inv[qq], wacc[kb][0]);
                    wacc[kb][1] = fmaf(a[kb][qq][1], inv[qq], wacc[kb][1]);
                }
            }
        }
    }

#pragma unroll
    for (int kb = 0; kb < 4; kb++) {
        if (kb < nb) {
            int k = kb * 64 + lane * 2;
            if (k < Lc)     atomicAdd(&sw[WC_OFF + k],     wacc[kb][0]);
            if (k + 1 < Lc) atomicAdd(&sw[WC_OFF + k + 1], wacc[kb][1]);
        }
    }
    __syncthreads();

    // ---- phase 3: S[c] = sum_k wc[k] * V[k][c] ----
    {
        const int c = tid & 15, part = tid >> 4;
        float acc = 0.f;
        for (int k = part; k < len; k += 16)
            acc = fmaf(sw[WC_OFF + k], sw[VS_OFF + k * 16 + c], acc);
        sw[SP_OFF + part * 16 + c] = acc;
    }
    __syncthreads();
    if (tid < 16) {
        float s = 0.f;
#pragma unroll
        for (int p = 0; p < 16; p++) s += sw[SP_OFF + p * 16 + tid];
        sw[SP_OFF + tid] = s;   // own slot: safe (only p=0 term read by self)
    }
    __syncthreads();

    // ---- phase 4 (fused): out[b][e] += inv*(S_head . Wf[e, h*16:]) (+ bf term on h==0) ----
    if (tid < 64) {
        float acc = 0.f;
        const float* wfr = Wf + tid * 64 + h * 16;
#pragma unroll
        for (int i = 0; i < 16; i++)
            acc = fmaf(sw[SP_OFF + i], wfr[i], acc);
        const float lenf = (float)len;
        const float invd = 1.0f / (lenf + 1e-8f);
        float val = acc * invd;
        if (h == 0) val = fmaf(bf[tid], lenf * invd, val);
        atomicAdd(out + b * 64 + tid, val);
    }
}

extern "C" void kernel_launch(void* const* d_in, const int* in_sizes, int n_in,
                              void* d_out, int out_size) {
    const float* input   = (const float*)d_in[0];
    const int*   mask    = (const int*)d_in[1];
    const float* pos_enc = (const float*)d_in[2];
    const float* Wk      = (const float*)d_in[3];
    const float* bk      = (const float*)d_in[4];
    const float* Wv      = (const float*)d_in[5];
    const float* bv      = (const float*)d_in[6];
    const float* Wq      = (const float*)d_in[7];
    const float* bq      = (const float*)d_in[8];
    const float* Wf      = (const float*)d_in[9];
    const float* bf      = (const float*)d_in[10];
    float* out           = (float*)d_out;

    cudaMemsetAsync(out, 0, (size_t)Bc * Ec * sizeof(float), 0);

    const size_t smem1 = (size_t)SM1_F * sizeof(float);
    cudaFuncSetAttribute(attn_head_kernel,
                         cudaFuncAttributeMaxDynamicSharedMemorySize, (int)smem1);
    attn_head_kernel<<<Bc * 4, 256, smem1>>>(input, mask, pos_enc,
                                             Wk, bk, Wv, bv, Wq, bq, Wf, bf, out);
}

// round 9
// speedup vs baseline: 1.0699x; 1.0699x over previous
#include <cuda_runtime.h>

constexpr int Bc = 512;
constexpr int Lc = 200;
constexpr int Ec = 64;

// ---------------- smem layout (floats) ----------------
constexpr int WSP    = 54;                        // ws[64][54]: ws[j][c], c in [0,48): K|V|Q cols
constexpr int WS_OFF = 0;
constexpr int XTP    = 132;                       // xT[64][132]: xT[j][t_local]
constexpr int XT_OFF = WS_OFF + 64 * WSP;         // 3456
constexpr int KTS    = 208;                       // kt[16][208]: kt[d][t]
constexpr int KT_OFF = XT_OFF + 64 * XTP;         // 11904
constexpr int QS_OFF = KT_OFF + 16 * KTS;         // q[200][16] (pre-scaled by 0.25*log2e)
constexpr int VS_OFF = QS_OFF + Lc * 16;          // v[200][16]
constexpr int WC_OFF = VS_OFF + Lc * 16;          // col sums [200]
constexpr int SP_OFF = WC_OFF + Lc + 8;           // partials [16][16]
constexpr int SM1_F  = SP_OFF + 256;              // 22096 floats = 88384 B

__device__ __forceinline__ float ex2f(float x) {
    float y;
    asm("ex2.approx.ftz.f32 %0, %1;" : "=f"(y) : "f"(x));
    return y;
}

extern __shared__ float sw[];

__global__ void __launch_bounds__(256, 2)
attn_head_kernel(const float* __restrict__ input,
                 const int* __restrict__ mask,
                 const float* __restrict__ pos_enc,
                 const float* __restrict__ Wk, const float* __restrict__ bk,
                 const float* __restrict__ Wv, const float* __restrict__ bv,
                 const float* __restrict__ Wq, const float* __restrict__ bq,
                 const float* __restrict__ Wf, const float* __restrict__ bf,
                 float* __restrict__ out) {
    const int tid  = threadIdx.x;
    const int lane = tid & 31;
    const int wid  = tid >> 5;
    const int b    = blockIdx.x >> 2;
    const int h    = blockIdx.x & 3;

    // ---- len (prefix mask; mask is int32) ----
    int pred = (tid < Lc) && (mask[(size_t)b * Lc + tid] != 0);
    const int len = __syncthreads_count(pred);

    // ---- phase 0: weights j-major: ws[j][c], c = m*16+i ----
    for (int idx = tid; idx < 64 * 48; idx += 256) {
        int c = idx >> 6, j = idx & 63;
        int m = c >> 4, i = c & 15;
        const float* Wm = (m == 0) ? Wk : ((m == 1) ? Wv : Wq);
        sw[WS_OFF + j * WSP + c] = Wm[(h * 16 + i) * 64 + j];
    }
    if (tid < Lc) sw[WC_OFF + tid] = 0.0f;
    __syncthreads();

    // ---- phase 1: register-tiled GEMM [len,64]x[64,48] ----
    // threadgrid: 32 rowgrps (4 rows) x 8 colgrps (6 cols); tile = 128 rows
    const int rowgrp = tid >> 3;          // 0..31
    const int colgrp = tid & 7;           // 0..7
    const int R0 = rowgrp * 4;            // local row base
    const int c0 = colgrp * 6;            // output col base (0..42)
    const float QSC = 0.36067376022224085f;   // 0.25 * log2(e)

    float bias[6];
#pragma unroll
    for (int cc = 0; cc < 6; cc++) {
        int c = c0 + cc, m = c >> 4, i = c & 15;
        bias[cc] = (m == 0) ? bk[h * 16 + i] : ((m == 1) ? bv[h * 16 + i] : bq[h * 16 + i]);
    }

    const int ntiles = (len + 127) >> 7;
    for (int tile = 0; tile < ntiles; tile++) {
        const int tb = tile * 128;
        const float4* in4 = (const float4*)(input + ((size_t)b * Lc + tb) * Ec);
        const float4* pe4 = (const float4*)(pos_enc + (size_t)tb * Ec);
#pragma unroll
        for (int v = 0; v < 8; v++) {
            int f = tid + v * 256;            // 0..2047
            int t = f >> 4, e0 = (f & 15) * 4;
            float4 val = make_float4(0.f, 0.f, 0.f, 0.f);
            if (tb + t < Lc) {
                float4 a = in4[f], p = pe4[f];
                val = make_float4(a.x + p.x, a.y + p.y, a.z + p.z, a.w + p.w);
            }
            sw[XT_OFF + (e0 + 0) * XTP + t] = val.x;
            sw[XT_OFF + (e0 + 1) * XTP + t] = val.y;
            sw[XT_OFF + (e0 + 2) * XTP + t] = val.z;
            sw[XT_OFF + (e0 + 3) * XTP + t] = val.w;
        }
        __syncthreads();

        if (tb + R0 < len) {
            float acc[4][6];
#pragma unroll
            for (int rr = 0; rr < 4; rr++)
#pragma unroll
                for (int cc = 0; cc < 6; cc++) acc[rr][cc] = 0.f;

#pragma unroll 8
            for (int j = 0; j < 64; j++) {
                float4 xv = *(const float4*)(sw + XT_OFF + j * XTP + R0);
                const float* wr = sw + WS_OFF + j * WSP + c0;
                float2 w01 = *(const float2*)(wr + 0);
                float2 w23 = *(const float2*)(wr + 2);
                float2 w45 = *(const float2*)(wr + 4);
                float wv[6] = {w01.x, w01.y, w23.x, w23.y, w45.x, w45.y};
                float xr[4] = {xv.x, xv.y, xv.z, xv.w};
#pragma unroll
                for (int rr = 0; rr < 4; rr++)
#pragma unroll
                    for (int cc = 0; cc < 6; cc++)
                        acc[rr][cc] = fmaf(xr[rr], wv[cc], acc[rr][cc]);
            }

#pragma unroll
            for (int rr = 0; rr < 4; rr++) {
                int t = tb + R0 + rr;
                if (t < len) {
#pragma unroll
                    for (int cc = 0; cc < 6; cc++) {
                        int c = c0 + cc;
                        float v = acc[rr][cc] + bias[cc];
                        if (c < 16)       sw[KT_OFF + c * KTS + t] = v;
                        else if (c < 32)  sw[VS_OFF + t * 16 + (c - 16)] = v;
                        else              sw[QS_OFF + t * 16 + (c - 32)] = v * QSC;
                    }
                }
            }
        }
        __syncthreads();
    }

    // ---- phase 2 (round-5 verbatim): scores + softmax + column sums ----
    // lane owns keys k = kb*64 + lane*2 + {0,1}; 4 query rows per warp iteration
    const int nb = (len + 63) >> 6;              // 1..4 k-blocks of 64
    float wacc[4][2];
#pragma unroll
    for (int kb = 0; kb < 4; kb++) { wacc[kb][0] = 0.f; wacc[kb][1] = 0.f; }

    for (int qb = wid * 4; qb < len; qb += 32) {
        float qv[4][16];
#pragma unroll
        for (int qq = 0; qq < 4; qq++) {
            int q = qb + qq; q = (q < len) ? q : 0;
            const float4* p = (const float4*)(sw + QS_OFF + q * 16);
#pragma unroll
            for (int jj = 0; jj < 4; jj++) {
                float4 v = p[jj];
                qv[qq][4 * jj + 0] = v.x; qv[qq][4 * jj + 1] = v.y;
                qv[qq][4 * jj + 2] = v.z; qv[qq][4 * jj + 3] = v.w;
            }
        }

        float ee[4][4][2];                        // [kb][q][key]
        float z[4] = {0.f, 0.f, 0.f, 0.f};
#pragma unroll
        for (int kb = 0; kb < 4; kb++) {
            if (kb < nb) {
                const int k0 = kb * 64 + lane * 2;
                const float* kp = sw + KT_OFF + k0;
                float a0[4], a1[4];
#pragma unroll
                for (int qq = 0; qq < 4; qq++) { a0[qq] = 0.f; a1[qq] = 0.f; }
#pragma unroll
                for (int j = 0; j < 16; j++) {
                    float2 kt2 = *(const float2*)(kp + j * KTS);
#pragma unroll
                    for (int qq = 0; qq < 4; qq++) {
                        a0[qq] = fmaf(kt2.x, qv[qq][j], a0[qq]);
                        a1[qq] = fmaf(kt2.y, qv[qq][j], a1[qq]);
                    }
                }
                const bool ok0 = (k0 + 0) < len;
                const bool ok1 = (k0 + 1) < len;
#pragma unroll
                for (int qq = 0; qq < 4; qq++) {
                    float e0 = ok0 ? ex2f(a0[qq]) : 0.f;
                    float e1 = ok1 ? ex2f(a1[qq]) : 0.f;
                    ee[kb][qq][0] = e0; ee[kb][qq][1] = e1;
                    z[qq] += e0 + e1;
                }
            } else {
#pragma unroll
                for (int qq = 0; qq < 4; qq++) { ee[kb][qq][0] = 0.f; ee[kb][qq][1] = 0.f; }
            }
        }

#pragma unroll
        for (int o = 16; o; o >>= 1) {
            z[0] += __shfl_xor_sync(0xffffffffu, z[0], o);
            z[1] += __shfl_xor_sync(0xffffffffu, z[1], o);
            z[2] += __shfl_xor_sync(0xffffffffu, z[2], o);
            z[3] += __shfl_xor_sync(0xffffffffu, z[3], o);
        }
        float inv[4];
#pragma unroll
        for (int qq = 0; qq < 4; qq++)
            inv[qq] = (qb + qq < len) ? __fdividef(1.0f, z[qq]) : 0.0f;
#pragma unroll
        for (int kb = 0; kb < 4; kb++) {
            if (kb < nb) {
#pragma unroll
                for (int qq = 0; qq < 4; qq++) {
                    wacc[kb][0] = fmaf(ee[kb][qq][0], inv[qq], wacc[kb][0]);
                    wacc[kb][1] = fmaf(ee[kb][qq][1], inv[qq], wacc[kb][1]);
                }
            }
        }
    }

#pragma unroll
    for (int kb = 0; kb < 4; kb++) {
        if (kb < nb) {
            int k = kb * 64 + lane * 2;
            if (k < Lc)     atomicAdd(&sw[WC_OFF + k],     wacc[kb][0]);
            if (k + 1 < Lc) atomicAdd(&sw[WC_OFF + k + 1], wacc[kb][1]);
        }
    }
    __syncthreads();

    // ---- phase 3: S[c] = sum_k wc[k] * V[k][c] ----
    {
        const int c = tid & 15, part = tid >> 4;
        float acc = 0.f;
        for (int k = part; k < len; k += 16)
            acc = fmaf(sw[WC_OFF + k], sw[VS_OFF + k * 16 + c], acc);
        sw[SP_OFF + part * 16 + c] = acc;
    }
    __syncthreads();
    if (tid < 16) {
        float s = 0.f;
#pragma unroll
        for (int p = 0; p < 16; p++) s += sw[SP_OFF + p * 16 + tid];
        sw[SP_OFF + tid] = s;   // own slot: safe (only p=0 term read by self)
    }
    __syncthreads();

    // ---- phase 4 (fused): out[b][e] += inv*(S_head . Wf[e, h*16:]) (+ bf term on h==0) ----
    if (tid < 64) {
        float acc = 0.f;
        const float* wfr = Wf + tid * 64 + h * 16;
#pragma unroll
        for (int i = 0; i < 16; i++)
            acc = fmaf(sw[SP_OFF + i], wfr[i], acc);
        const float lenf = (float)len;
        const float invd = 1.0f / (lenf + 1e-8f);
        float val = acc * invd;
        if (h == 0) val = fmaf(bf[tid], lenf * invd, val);
        atomicAdd(out + b * 64 + tid, val);
    }
}

extern "C" void kernel_launch(void* const* d_in, const int* in_sizes, int n_in,
                              void* d_out, int out_size) {
    const float* input   = (const float*)d_in[0];
    const int*   mask    = (const int*)d_in[1];
    const float* pos_enc = (const float*)d_in[2];
    const float* Wk      = (const float*)d_in[3];
    const float* bk      = (const float*)d_in[4];
    const float* Wv      = (const float*)d_in[5];
    const float* bv      = (const float*)d_in[6];
    const float* Wq      = (const float*)d_in[7];
    const float* bq      = (const float*)d_in[8];
    const float* Wf      = (const float*)d_in[9];
    const float* bf      = (const float*)d_in[10];
    float* out           = (float*)d_out;

    cudaMemsetAsync(out, 0, (size_t)Bc * Ec * sizeof(float), 0);

    const size_t smem1 = (size_t)SM1_F * sizeof(float);
    cudaFuncSetAttribute(attn_head_kernel,
                         cudaFuncAttributeMaxDynamicSharedMemorySize, (int)smem1);
    attn_head_kernel<<<Bc * 4, 256, smem1>>>(input, mask, pos_enc,
                                             Wk, bk, Wv, bv, Wq, bq, Wf, bf, out);
}

// round 10
// speedup vs baseline: 1.2164x; 1.1369x over previous
#include <cuda_runtime.h>

constexpr int Bc = 512;
constexpr int Lc = 200;
constexpr int Ec = 64;

// ---------------- smem layout (floats) ----------------
constexpr int WTP    = 68;                        // wT[48][68]: wT[c][j]
constexpr int WT_OFF = 0;
constexpr int XSS    = 68;                        // xs[128][68] row-major
constexpr int XS_OFF = WT_OFF + 48 * WTP;         // 3264
constexpr int KTS    = 208;                       // kt[16][208]: kt[d][t]
constexpr int KT_OFF = XS_OFF + 128 * XSS;        // 11968
constexpr int QS_OFF = KT_OFF + 16 * KTS;         // q[200][16] (pre-scaled by 0.25*log2e)
constexpr int VS_OFF = QS_OFF + Lc * 16;          // v[200][16]
constexpr int WC_OFF = VS_OFF + Lc * 16;          // col sums [200]
constexpr int SP_OFF = WC_OFF + Lc + 8;           // partials [16][16]
constexpr int SM1_F  = SP_OFF + 256;              // 22160 floats = 88640 B

__device__ __forceinline__ float ex2f(float x) {
    float y;
    asm("ex2.approx.ftz.f32 %0, %1;" : "=f"(y) : "f"(x));
    return y;
}

extern __shared__ float sw[];

__global__ void __launch_bounds__(256, 2)
attn_head_kernel(const float* __restrict__ input,
                 const int* __restrict__ mask,
                 const float* __restrict__ pos_enc,
                 const float* __restrict__ Wk, const float* __restrict__ bk,
                 const float* __restrict__ Wv, const float* __restrict__ bv,
                 const float* __restrict__ Wq, const float* __restrict__ bq,
                 const float* __restrict__ Wf, const float* __restrict__ bf,
                 float* __restrict__ out) {
    const int tid  = threadIdx.x;
    const int lane = tid & 31;
    const int wid  = tid >> 5;
    const int b    = blockIdx.x >> 2;
    const int h    = blockIdx.x & 3;

    // ---- len (prefix mask; mask is int32) ----
    int pred = (tid < Lc) && (mask[(size_t)b * Lc + tid] != 0);
    const int len = __syncthreads_count(pred);

    // ---- phase 0: weights transposed: wT[c][j], c = m*16+i ----
    // lanes span j -> coalesced LDG, contiguous STS (conflict-free)
    for (int idx = tid; idx < 64 * 48; idx += 256) {
        int c = idx >> 6, j = idx & 63;
        int m = c >> 4, i = c & 15;
        const float* Wm = (m == 0) ? Wk : ((m == 1) ? Wv : Wq);
        sw[WT_OFF + c * WTP + j] = Wm[(h * 16 + i) * 64 + j];
    }
    if (tid < Lc) sw[WC_OFF + tid] = 0.0f;
    __syncthreads();

    // ---- phase 1: register-tiled GEMM [len,64]x[64,48], j-vectorized ----
    // thread rows: rowgrp + 32*rr (rr=0..3); thread cols: colgrp + 8*s (s=0..5)
    const int rowgrp = tid >> 3;          // 0..31
    const int colgrp = tid & 7;           // 0..7
    const float QSC = 0.36067376022224085f;   // 0.25 * log2(e)

    float bias[6];
#pragma unroll
    for (int s = 0; s < 6; s++) {
        int c = colgrp + 8 * s, m = c >> 4, i = c & 15;
        bias[s] = (m == 0) ? bk[h * 16 + i] : ((m == 1) ? bv[h * 16 + i] : bq[h * 16 + i]);
    }

    const int ntiles = (len + 127) >> 7;
    for (int tile = 0; tile < ntiles; tile++) {
        const int tb = tile * 128;
        // stage xs[t][e] = input + pos_enc  (row-major, conflict-free float4)
        const float4* in4 = (const float4*)(input + ((size_t)b * Lc + tb) * Ec);
        const float4* pe4 = (const float4*)(pos_enc + (size_t)tb * Ec);
#pragma unroll
        for (int v = 0; v < 8; v++) {
            int f = tid + v * 256;            // 0..2047
            int t = f >> 4, e0 = (f & 15) * 4;
            float4 val = make_float4(0.f, 0.f, 0.f, 0.f);
            if (tb + t < Lc) {
                float4 a = in4[f], p = pe4[f];
                val = make_float4(a.x + p.x, a.y + p.y, a.z + p.z, a.w + p.w);
            }
            *(float4*)(sw + XS_OFF + t * XSS + e0) = val;
        }
        __syncthreads();

        if (tb + rowgrp < len) {
            float acc[4][6];
#pragma unroll
            for (int rr = 0; rr < 4; rr++)
#pragma unroll
                for (int s = 0; s < 6; s++) acc[rr][s] = 0.f;

#pragma unroll
            for (int j4 = 0; j4 < 64; j4 += 4) {
                float4 xv[4];
#pragma unroll
                for (int rr = 0; rr < 4; rr++)
                    xv[rr] = *(const float4*)(sw + XS_OFF + (rowgrp + 32 * rr) * XSS + j4);
#pragma unroll
                for (int s = 0; s < 6; s++) {
                    float4 wq = *(const float4*)(sw + WT_OFF + (colgrp + 8 * s) * WTP + j4);
#pragma unroll
                    for (int rr = 0; rr < 4; rr++) {
                        acc[rr][s] = fmaf(xv[rr].x, wq.x, acc[rr][s]);
                        acc[rr][s] = fmaf(xv[rr].y, wq.y, acc[rr][s]);
                        acc[rr][s] = fmaf(xv[rr].z, wq.z, acc[rr][s]);
                        acc[rr][s] = fmaf(xv[rr].w, wq.w, acc[rr][s]);
                    }
                }
            }

            // epilogue: scatter into kt / vs / qs
#pragma unroll
            for (int rr = 0; rr < 4; rr++) {
                int t = tb + rowgrp + 32 * rr;
                if (t < len) {
#pragma unroll
                    for (int s = 0; s < 6; s++) {
                        int c = colgrp + 8 * s;
                        float v = acc[rr][s] + bias[s];
                        if (c < 16)       sw[KT_OFF + c * KTS + t] = v;
                        else if (c < 32)  sw[VS_OFF + t * 16 + (c - 16)] = v;
                        else              sw[QS_OFF + t * 16 + (c - 32)] = v * QSC;
                    }
                }
            }
        }
        __syncthreads();
    }

    // ---- phase 2 (round-5 verbatim): scores + softmax + column sums ----
    // lane owns keys k = kb*64 + lane*2 + {0,1}; 4 query rows per warp iteration
    const int nb = (len + 63) >> 6;              // 1..4 k-blocks of 64
    float wacc[4][2];
#pragma unroll
    for (int kb = 0; kb < 4; kb++) { wacc[kb][0] = 0.f; wacc[kb][1] = 0.f; }

    for (int qb = wid * 4; qb < len; qb += 32) {
        float qv[4][16];
#pragma unroll
        for (int qq = 0; qq < 4; qq++) {
            int q = qb + qq; q = (q < len) ? q : 0;
            const float4* p = (const float4*)(sw + QS_OFF + q * 16);
#pragma unroll
            for (int jj = 0; jj < 4; jj++) {
                float4 v = p[jj];
                qv[qq][4 * jj + 0] = v.x; qv[qq][4 * jj + 1] = v.y;
                qv[qq][4 * jj + 2] = v.z; qv[qq][4 * jj + 3] = v.w;
            }
        }

        float ee[4][4][2];                        // [kb][q][key]
        float z[4] = {0.f, 0.f, 0.f, 0.f};
#pragma unroll
        for (int kb = 0; kb < 4; kb++) {
            if (kb < nb) {
                const int k0 = kb * 64 + lane * 2;
                const float* kp = sw + KT_OFF + k0;
                float a0[4], a1[4];
#pragma unroll
                for (int qq = 0; qq < 4; qq++) { a0[qq] = 0.f; a1[qq] = 0.f; }
#pragma unroll
                for (int j = 0; j < 16; j++) {
                    float2 kt2 = *(const float2*)(kp + j * KTS);
#pragma unroll
                    for (int qq = 0; qq < 4; qq++) {
                        a0[qq] = fmaf(kt2.x, qv[qq][j], a0[qq]);
                        a1[qq] = fmaf(kt2.y, qv[qq][j], a1[qq]);
                    }
                }
                const bool ok0 = (k0 + 0) < len;
                const bool ok1 = (k0 + 1) < len;
#pragma unroll
                for (int qq = 0; qq < 4; qq++) {
                    float e0 = ok0 ? ex2f(a0[qq]) : 0.f;
                    float e1 = ok1 ? ex2f(a1[qq]) : 0.f;
                    ee[kb][qq][0] = e0; ee[kb][qq][1] = e1;
                    z[qq] += e0 + e1;
                }
            } else {
#pragma unroll
                for (int qq = 0; qq < 4; qq++) { ee[kb][qq][0] = 0.f; ee[kb][qq][1] = 0.f; }
            }
        }

#pragma unroll
        for (int o = 16; o; o >>= 1) {
            z[0] += __shfl_xor_sync(0xffffffffu, z[0], o);
            z[1] += __shfl_xor_sync(0xffffffffu, z[1], o);
            z[2] += __shfl_xor_sync(0xffffffffu, z[2], o);
            z[3] += __shfl_xor_sync(0xffffffffu, z[3], o);
        }
        float inv[4];
#pragma unroll
        for (int qq = 0; qq < 4; qq++)
            inv[qq] = (qb + qq < len) ? __fdividef(1.0f, z[qq]) : 0.0f;
#pragma unroll
        for (int kb = 0; kb < 4; kb++) {
            if (kb < nb) {
#pragma unroll
                for (int qq = 0; qq < 4; qq++) {
                    wacc[kb][0] = fmaf(ee[kb][qq][0], inv[qq], wacc[kb][0]);
                    wacc[kb][1] = fmaf(ee[kb][qq][1], inv[qq], wacc[kb][1]);
                }
            }
        }
    }

#pragma unroll
    for (int kb = 0; kb < 4; kb++) {
        if (kb < nb) {
            int k = kb * 64 + lane * 2;
            if (k < Lc)     atomicAdd(&sw[WC_OFF + k],     wacc[kb][0]);
            if (k + 1 < Lc) atomicAdd(&sw[WC_OFF + k + 1], wacc[kb][1]);
        }
    }
    __syncthreads();

    // ---- phase 3: S[c] = sum_k wc[k] * V[k][c] ----
    {
        const int c = tid & 15, part = tid >> 4;
        float acc = 0.f;
        for (int k = part; k < len; k += 16)
            acc = fmaf(sw[WC_OFF + k], sw[VS_OFF + k * 16 + c], acc);
        sw[SP_OFF + part * 16 + c] = acc;
    }
    __syncthreads();
    if (tid < 16) {
        float s = 0.f;
#pragma unroll
        for (int p = 0; p < 16; p++) s += sw[SP_OFF + p * 16 + tid];
        sw[SP_OFF + tid] = s;   // own slot: safe (only p=0 term read by self)
    }
    __syncthreads();

    // ---- phase 4 (fused): out[b][e] += inv*(S_head . Wf[e, h*16:]) (+ bf term on h==0) ----
    if (tid < 64) {
        float acc = 0.f;
        const float* wfr = Wf + tid * 64 + h * 16;
#pragma unroll
        for (int i = 0; i < 16; i++)
            acc = fmaf(sw[SP_OFF + i], wfr[i], acc);
        const float lenf = (float)len;
        const float invd = 1.0f / (lenf + 1e-8f);
        float val = acc * invd;
        if (h == 0) val = fmaf(bf[tid], lenf * invd, val);
        atomicAdd(out + b * 64 + tid, val);
    }
}

extern "C" void kernel_launch(void* const* d_in, const int* in_sizes, int n_in,
                              void* d_out, int out_size) {
    const float* input   = (const float*)d_in[0];
    const int*   mask    = (const int*)d_in[1];
    const float* pos_enc = (const float*)d_in[2];
    const float* Wk      = (const float*)d_in[3];
    const float* bk      = (const float*)d_in[4];
    const float* Wv      = (const float*)d_in[5];
    const float* bv      = (const float*)d_in[6];
    const float* Wq      = (const float*)d_in[7];
    const float* bq      = (const float*)d_in[8];
    const float* Wf      = (const float*)d_in[9];
    const float* bf      = (const float*)d_in[10];
    float* out           = (float*)d_out;

    cudaMemsetAsync(out, 0, (size_t)Bc * Ec * sizeof(float), 0);

    const size_t smem1 = (size_t)SM1_F * sizeof(float);
    cudaFuncSetAttribute(attn_head_kernel,
                         cudaFuncAttributeMaxDynamicSharedMemorySize, (int)smem1);
    attn_head_kernel<<<Bc * 4, 256, smem1>>>(input, mask, pos_enc,
                                             Wk, bk, Wv, bv, Wq, bq, Wf, bf, out);
}